// round 4
// baseline (speedup 1.0000x reference)
#include <cuda_runtime.h>

#define BB 4
#define CC 256
#define HH 256
#define WW 256
#define HWSZ (HH * WW)
#define NPIX (BB * HWSZ)

// Per-pixel precomputed maps (channel-independent).
// g_info bits: 0 = gt class (0/1), 1 = correct (pred==gt), 2 = edge
__device__ unsigned char g_info[NPIX];
// g_msecnt: 0 if pixel not mse-masked, else cnt_corr (1..24)
__device__ unsigned char g_msecnt[NPIX];
__device__ double g_loss[2];
__device__ int g_nsel[2];
__device__ int g_cal[2];

// ---------------- Kernel A: per-pixel info (pred, correct, edge) -----------
__global__ void kernA(const int* __restrict__ gt, const float* __restrict__ clf) {
    int p = blockIdx.x * blockDim.x + threadIdx.x;
    if (p == 0) {
        g_loss[0] = 0.0; g_loss[1] = 0.0;
        g_nsel[0] = 0; g_nsel[1] = 0;
        g_cal[0] = 0; g_cal[1] = 0;
    }
    int b = p >> 16;
    int hw = p & (HWSZ - 1);
    int h = hw >> 8;
    int w = hw & (WW - 1);
    int g = gt[p];
    float c0 = clf[(size_t)(b * 2) * HWSZ + hw];
    float c1 = clf[(size_t)(b * 2 + 1) * HWSZ + hw];
    int pred = (c1 > c0) ? 1 : 0;               // argmax ties -> index 0
    int correct = (pred == g) ? 1 : 0;
    int edge = (g == -1) ? 1 : 0;
    if (h < HH - 5) edge |= (gt[p + 5 * WW] != g) ? 1 : 0;
    if (w < WW - 5) edge |= (gt[p + 5] != g) ? 1 : 0;
    g_info[p] = (unsigned char)((g & 1) | (correct << 1) | (edge << 2));
}

// ---------------- Kernel B: ring counts, mse/cal masks, counters -----------
__global__ void kernB() {
    int p = blockIdx.x * blockDim.x + threadIdx.x;
    int hw = p & (HWSZ - 1);
    int h = hw >> 8;
    int w = hw & (WW - 1);
    unsigned info = g_info[p];
    int g = info & 1;
    int correct = (info >> 1) & 1;
    int edge = (info >> 2) & 1;
    int cntCorr = 0, cntCls = 0;
#pragma unroll
    for (int dh = -2; dh <= 2; dh++) {
#pragma unroll
        for (int dw = -2; dw <= 2; dw++) {
            if (dh == 0 && dw == 0) continue;
            int hh = h + dh, wp = w + dw;
            if ((unsigned)hh < HH && (unsigned)wp < WW) {
                unsigned qi = g_info[p + dh * WW + dw];
                int same = ((int)(qi & 1) == g) ? 1 : 0;
                cntCls += same;
                cntCorr += same & (int)((qi >> 1) & 1);
            }
        }
    }
    int mse = correct & edge & (cntCorr >= 1 ? 1 : 0);
    int cal = edge & (cntCls >= 1 ? 1 : 0);
    g_msecnt[p] = (unsigned char)(mse ? cntCorr : 0);

    unsigned bm;
    bm = __ballot_sync(0xFFFFFFFFu, mse && g == 0);
    if ((threadIdx.x & 31) == 0 && bm) atomicAdd(&g_nsel[0], __popc(bm));
    bm = __ballot_sync(0xFFFFFFFFu, mse && g == 1);
    if ((threadIdx.x & 31) == 0 && bm) atomicAdd(&g_nsel[1], __popc(bm));
    bm = __ballot_sync(0xFFFFFFFFu, cal && g == 0);
    if ((threadIdx.x & 31) == 0 && bm) atomicAdd(&g_cal[0], __popc(bm));
    bm = __ballot_sync(0xFFFFFFFFu, cal && g == 1);
    if ((threadIdx.x & 31) == 0 && bm) atomicAdd(&g_cal[1], __popc(bm));
}

// ---------------- Kernel C: main loss (separable 2-class box filter) -------
// Block (32,8)=256 thr. Lane tx loads float2 of cols wl=w0-2+2tx; outputs are
// the 60 cols [w0, w0+59] (lanes 1..30, 2 cols each). ty owns 4 output rows;
// loads 8 rows from ONE clamped base + uniform i*WW offsets (2 addr regs).
// Window shift d = (h0+cr0)-start_row in {0,2,4}, warp-uniform: d==2 takes the
// fast sliding-window path; boundary warps take a generic predicated path.
// Column sums for both classes go to double-buffered smem (one barrier per
// channel); horizontal pass reads 3 float2 per (output,class). Smem layout is
// shifted +1 float2 so halo reads need no clamp. Low regs -> occupancy 3.
#define TOUT 60
#define NCHUNK 16
#define CHPER (CC / NCHUNK)
#define CSTRIDE 68
#define PLANE (32 * CSTRIDE)
#define CS_BYTES (2 * 2 * PLANE * 4)   // 34816 B

__global__ void __launch_bounds__(256, 3) kernC(const float* __restrict__ x) {
    extern __shared__ float cs_s[];
    __shared__ float red0[256], red1[256];

    const int tx = threadIdx.x, ty = threadIdx.y;
    const int tid = (ty << 5) | tx;
    const int b = blockIdx.z >> 4;
    const int chunk = blockIdx.z & (NCHUNK - 1);
    const int h0 = blockIdx.y << 5;
    const int w0 = blockIdx.x * TOUT;
    const int cr0 = ty << 2;
    const int wl = w0 - 2 + (tx << 1);
    const bool colOK = ((unsigned)wl <= 254u);
    const int wc = colOK ? wl : (wl < 0 ? 0 : 254);
    int sr = h0 + cr0 - 2;
    const int start_row = sr < 0 ? 0 : (sr > HH - 8 ? HH - 8 : sr);
    const int d = h0 + cr0 - start_row;          // 0, 2, or 4 (warp-uniform)
    const int base_px = start_row * WW + wc;

    const unsigned char* infoB = g_info + (size_t)b * HWSZ;
    const unsigned char* mseB = g_msecnt + (size_t)b * HWSZ;

    // per-row class coefficients for the 8 loaded rows
    float2 fc0[8], fc1[8];
#pragma unroll
    for (int i = 0; i < 8; i++) {
        float a0 = 0.f, a1 = 0.f, b0v = 0.f, b1v = 0.f;
        if (colOK) {
            unsigned qa = infoB[base_px + i * WW];
            unsigned qb = infoB[base_px + i * WW + 1];
            int ga = qa & 1, ca = (qa >> 1) & 1;
            int gb = qb & 1, cb = (qb >> 1) & 1;
            a1 = (ca & ga) ? 1.f : 0.f;
            a0 = (ca & (ga ^ 1)) ? 1.f : 0.f;
            b1v = (cb & gb) ? 1.f : 0.f;
            b0v = (cb & (gb ^ 1)) ? 1.f : 0.f;
        }
        fc0[i] = make_float2(a0, b0v);
        fc1[i] = make_float2(a1, b1v);
    }

    // per-output-pixel constants (4 rows x 2 cols)
    const bool lOK = (tx >= 1) && (tx <= 30);
    float inv[4][2];
    int mskb = 0, clsb = 0;
#pragma unroll
    for (int r = 0; r < 4; r++) {
#pragma unroll
        for (int j = 0; j < 2; j++) {
            int col = wl + j;
            bool o = lOK && (col <= 255);
            int off = (h0 + cr0 + r) * WW + (o ? col : 0);
            unsigned char mc = o ? mseB[off] : (unsigned char)0;
            int cl = o ? (int)(infoB[off] & 1) : 0;
            inv[r][j] = 1.f / ((float)mc + 1e-5f);
            if (mc) mskb |= 1 << (r * 2 + j);
            if (cl) clsb |= 1 << (r * 2 + j);
        }
    }

    float acc0 = 0.f, acc1 = 0.f;
    const float* xbase = x + ((size_t)b * CC + (size_t)chunk * CHPER) * HWSZ + base_px;

    for (int ch = 0; ch < CHPER; ch++) {
        const float* xc = xbase + (size_t)ch * HWSZ;
        float2 xi[8];
#pragma unroll
        for (int i = 0; i < 8; i++)
            xi[i] = __ldg((const float2*)(xc + i * WW));

        const int buf = ch & 1;
        float* p0 = cs_s + buf * (2 * PLANE) + cr0 * CSTRIDE + ((tx + 1) << 1);
        float* p1 = p0 + PLANE;
        float2 cen[4];

        if (d == 2) {
            // fast sliding-window column sums (interior warps)
            float s0x = 0.f, s0y = 0.f, s1x = 0.f, s1y = 0.f;
#pragma unroll
            for (int i = 0; i < 5; i++) {
                s0x = fmaf(xi[i].x, fc0[i].x, s0x);
                s0y = fmaf(xi[i].y, fc0[i].y, s0y);
                s1x = fmaf(xi[i].x, fc1[i].x, s1x);
                s1y = fmaf(xi[i].y, fc1[i].y, s1y);
            }
            *(float2*)p0 = make_float2(s0x, s0y);
            *(float2*)p1 = make_float2(s1x, s1y);
#pragma unroll
            for (int r = 1; r < 4; r++) {
                s0x = fmaf(xi[r + 4].x, fc0[r + 4].x, s0x);
                s0x = fmaf(-xi[r - 1].x, fc0[r - 1].x, s0x);
                s0y = fmaf(xi[r + 4].y, fc0[r + 4].y, s0y);
                s0y = fmaf(-xi[r - 1].y, fc0[r - 1].y, s0y);
                s1x = fmaf(xi[r + 4].x, fc1[r + 4].x, s1x);
                s1x = fmaf(-xi[r - 1].x, fc1[r - 1].x, s1x);
                s1y = fmaf(xi[r + 4].y, fc1[r + 4].y, s1y);
                s1y = fmaf(-xi[r - 1].y, fc1[r - 1].y, s1y);
                *(float2*)(p0 + r * CSTRIDE) = make_float2(s0x, s0y);
                *(float2*)(p1 + r * CSTRIDE) = make_float2(s1x, s1y);
            }
            cen[0] = xi[2]; cen[1] = xi[3]; cen[2] = xi[4]; cen[3] = xi[5];
        } else {
            // boundary warps: shifted, clipped window (d = 0 or 4)
#pragma unroll
            for (int r = 0; r < 4; r++) {
                float s0x = 0.f, s0y = 0.f, s1x = 0.f, s1y = 0.f;
#pragma unroll
                for (int i = 0; i < 8; i++) {
                    if (i >= r + d - 2 && i <= r + d + 2) {
                        s0x = fmaf(xi[i].x, fc0[i].x, s0x);
                        s0y = fmaf(xi[i].y, fc0[i].y, s0y);
                        s1x = fmaf(xi[i].x, fc1[i].x, s1x);
                        s1y = fmaf(xi[i].y, fc1[i].y, s1y);
                    }
                }
                *(float2*)(p0 + r * CSTRIDE) = make_float2(s0x, s0y);
                *(float2*)(p1 + r * CSTRIDE) = make_float2(s1x, s1y);
            }
#pragma unroll
            for (int r = 0; r < 4; r++)
#pragma unroll
                for (int i = 0; i < 8; i++)
                    if (d + r == i) cen[r] = xi[i];
        }
        __syncthreads();  // single barrier per channel (double-buffered csum)

        // masked horizontal pass
        const float* hb = cs_s + buf * (2 * PLANE);
#pragma unroll
        for (int r = 0; r < 4; r++) {
            const int rowf = (cr0 + r) * CSTRIDE;
            {   // j = 0 : window = cols lc-2..lc+2
                int cl = (clsb >> (r * 2)) & 1;
                const float2* rp = (const float2*)(hb + cl * PLANE + rowf);
                float2 A = rp[tx], B = rp[tx + 1], C = rp[tx + 2];
                if (mskb & (1 << (r * 2))) {
                    float rs = A.x + A.y + B.x + B.y + C.x;
                    float t = rs - cen[r].x;
                    float dd = fmaf(-t, inv[r][0], cen[r].x);
                    float q = dd * dd;
                    if (cl) acc1 += q; else acc0 += q;
                }
            }
            {   // j = 1 : window = cols lc-1..lc+3
                int cl = (clsb >> (r * 2 + 1)) & 1;
                const float2* rp = (const float2*)(hb + cl * PLANE + rowf);
                float2 A = rp[tx], B = rp[tx + 1], C = rp[tx + 2];
                if (mskb & (1 << (r * 2 + 1))) {
                    float rs = A.y + B.x + B.y + C.x + C.y;
                    float t = rs - cen[r].y;
                    float dd = fmaf(-t, inv[r][1], cen[r].y);
                    float q = dd * dd;
                    if (cl) acc1 += q; else acc0 += q;
                }
            }
        }
    }

    // block reduction -> 2 double atomics per block
    red0[tid] = acc0;
    red1[tid] = acc1;
    __syncthreads();
    for (int s = 128; s > 0; s >>= 1) {
        if (tid < s) { red0[tid] += red0[tid + s]; red1[tid] += red1[tid + s]; }
        __syncthreads();
    }
    if (tid == 0) {
        atomicAdd(&g_loss[0], (double)red0[0]);
        atomicAdd(&g_loss[1], (double)red1[0]);
    }
}

// ---------------- Kernel D: finalize ---------------------------------------
__global__ void kernD(float* out) {
    double total = 0.0;
    int ncls = 0;
#pragma unroll
    for (int c = 0; c < 2; c++) {
        bool valid = (g_cal[c] >= 1) && (g_nsel[c] >= 1);
        double denom = (double)g_nsel[c] * 256.0;
        if (denom < 1.0) denom = 1.0;
        double lc = g_loss[c] / denom;
        if (valid) { total += lc; ncls++; }
    }
    out[0] = (ncls == 0) ? 0.0f : (float)(total / (double)ncls);
}

extern "C" void kernel_launch(void* const* d_in, const int* in_sizes, int n_in,
                              void* d_out, int out_size) {
    const float* xfeat = (const float*)d_in[0];   // [4,256,256,256] f32
    const float* clf   = (const float*)d_in[1];   // [4,2,256,256]   f32
    const int*   gt    = (const int*)d_in[2];     // [4,256,256]     i32
    float* out = (float*)d_out;

    kernA<<<NPIX / 256, 256>>>(gt, clf);
    kernB<<<NPIX / 256, 256>>>();
    dim3 blk(32, 8);
    dim3 grd((WW + TOUT - 1) / TOUT, HH / 32, BB * NCHUNK);  // 5 x 8 x 64
    kernC<<<grd, blk, CS_BYTES>>>(xfeat);
    kernD<<<1, 1>>>(out);
}

// round 5
// speedup vs baseline: 1.3938x; 1.3938x over previous
#include <cuda_runtime.h>

#define BB 4
#define CC 256
#define HH 256
#define WW 256
#define HWSZ (HH * WW)
#define NPIX (BB * HWSZ)
#define FULLMASK 0xFFFFFFFFu

// Channel-independent per-pixel planes.
// g_info bits: 0 = gt class (0/1), 1 = correct (pred==gt), 2 = edge
__device__ unsigned char g_info[NPIX];
// fv: +1 if correct & class1, -1 if correct & class0, else 0
__device__ float g_fv[NPIX];
// invsel: 0 if not mse-masked; else +-1/(cnt_corr+1e-5), sign = class
__device__ float g_invsel[NPIX];
__device__ double g_loss[2];
__device__ int g_nsel[2];
__device__ int g_cal[2];

// ---------------- Kernel A: per-pixel info (pred, correct, edge) -----------
__global__ void kernA(const int* __restrict__ gt, const float* __restrict__ clf) {
    int p = blockIdx.x * blockDim.x + threadIdx.x;
    if (p == 0) {
        g_loss[0] = 0.0; g_loss[1] = 0.0;
        g_nsel[0] = 0; g_nsel[1] = 0;
        g_cal[0] = 0; g_cal[1] = 0;
    }
    int b = p >> 16;
    int hw = p & (HWSZ - 1);
    int h = hw >> 8;
    int w = hw & (WW - 1);
    int g = gt[p];
    float c0 = clf[(size_t)(b * 2) * HWSZ + hw];
    float c1 = clf[(size_t)(b * 2 + 1) * HWSZ + hw];
    int pred = (c1 > c0) ? 1 : 0;               // argmax ties -> index 0
    int correct = (pred == g) ? 1 : 0;
    int edge = (g == -1) ? 1 : 0;
    if (h < HH - 5) edge |= (gt[p + 5 * WW] != g) ? 1 : 0;
    if (w < WW - 5) edge |= (gt[p + 5] != g) ? 1 : 0;
    g_info[p] = (unsigned char)((g & 1) | (correct << 1) | (edge << 2));
}

// ---------------- Kernel B: ring counts -> fv / invsel planes + counters ---
__global__ void kernB() {
    int p = blockIdx.x * blockDim.x + threadIdx.x;
    int hw = p & (HWSZ - 1);
    int h = hw >> 8;
    int w = hw & (WW - 1);
    unsigned info = g_info[p];
    int g = info & 1;
    int correct = (info >> 1) & 1;
    int edge = (info >> 2) & 1;
    int cntCorr = 0, cntCls = 0;
#pragma unroll
    for (int dh = -2; dh <= 2; dh++) {
#pragma unroll
        for (int dw = -2; dw <= 2; dw++) {
            if (dh == 0 && dw == 0) continue;
            int hh = h + dh, wp = w + dw;
            if ((unsigned)hh < HH && (unsigned)wp < WW) {
                unsigned qi = g_info[p + dh * WW + dw];
                int same = ((int)(qi & 1) == g) ? 1 : 0;
                cntCls += same;
                cntCorr += same & (int)((qi >> 1) & 1);
            }
        }
    }
    int mse = correct & edge & (cntCorr >= 1 ? 1 : 0);
    int cal = edge & (cntCls >= 1 ? 1 : 0);

    g_fv[p] = correct ? (g ? 1.0f : -1.0f) : 0.0f;
    float inv = 1.0f / ((float)cntCorr + 1e-5f);
    g_invsel[p] = mse ? (g ? inv : -inv) : 0.0f;

    unsigned bm;
    bm = __ballot_sync(FULLMASK, mse && g == 0);
    if ((threadIdx.x & 31) == 0 && bm) atomicAdd(&g_nsel[0], __popc(bm));
    bm = __ballot_sync(FULLMASK, mse && g == 1);
    if ((threadIdx.x & 31) == 0 && bm) atomicAdd(&g_nsel[1], __popc(bm));
    bm = __ballot_sync(FULLMASK, cal && g == 0);
    if ((threadIdx.x & 31) == 0 && bm) atomicAdd(&g_cal[0], __popc(bm));
    bm = __ballot_sync(FULLMASK, cal && g == 1);
    if ((threadIdx.x & 31) == 0 && bm) atomicAdd(&g_cal[1], __popc(bm));
}

// ---------------- Kernel C: warp-autonomous separable box filter -----------
// Each warp owns (b, chunk, hband, wband): 8 channels x 30 output rows x 60
// output cols. Lane tx covers float2 cols wl = w0-2+2tx (64 cols incl. halo);
// lanes 1..30 produce outputs. Vertical: 5-slot register ring of per-class
// products, sliding column sums cs0/cs1. Horizontal: 8 warp shuffles per row.
// No smem, no __syncthreads in the main loop; x rows batch-prefetched 5 deep.
// Center x recovered as p0+p1 (= x*corr, and mse-masked => corr=1).
// Warp-task decode: gw = block*8+wid -> wband(5) x hband(9) x b(4) x chunk(32).
__global__ void __launch_bounds__(256, 3) kernC(const float* __restrict__ x) {
    __shared__ double sred[2][8];
    const int lane = threadIdx.x & 31;
    const int wid = threadIdx.x >> 5;
    const int gw = blockIdx.x * 8 + wid;       // [0, 5760)
    const int wband = gw % 5;
    const int rest = gw / 5;
    const int hband = rest % 9;
    const int cb = rest / 9;                   // [0, 128)
    const int b = cb >> 5;
    const int chunk = cb & 31;

    const int h0 = hband * 30;
    const int w0 = wband * 60;
    const int wl = w0 - 2 + (lane << 1);
    const bool colv = (wl >= 0) && (wl <= 254);
    const int wc = colv ? wl : (wl < 0 ? 0 : 254);
    const bool qv = colv && (lane >= 1) && (lane <= 30);

    const float* fvp = g_fv + b * HWSZ + wc;
    const float* ivp = g_invsel + b * HWSZ + wc;
    const float* xb = x + (((size_t)(b * CC + chunk * 8)) << 16) + wc;

    float acc0 = 0.f, acc1 = 0.f;

#pragma unroll 1
    for (int ch = 0; ch < 8; ch++) {
        const float* xc = xb + ((size_t)ch << 16);
        float2 p0r[5], p1r[5];
        float csx0 = 0.f, csy0 = 0.f, csx1 = 0.f, csy1 = 0.f;
        p0r[4] = make_float2(0.f, 0.f);
        p1r[4] = make_float2(0.f, 0.f);

        // prologue: rows h0-2 .. h0+1 into slots 0..3
#pragma unroll
        for (int k = 0; k < 4; k++) {
            int r = h0 - 2 + k;                 // <= 241, may be < 0
            int rc = r < 0 ? 0 : r;
            float2 xv = __ldg((const float2*)(xc + (rc << 8)));
            float2 fv = __ldg((const float2*)(fvp + (rc << 8)));
            if (!(colv && r >= 0)) { fv.x = 0.f; fv.y = 0.f; }
            float f1x = fmaxf(fv.x, 0.f), f1y = fmaxf(fv.y, 0.f);
            float f0x = f1x - fv.x, f0y = f1y - fv.y;
            p0r[k] = make_float2(xv.x * f0x, xv.y * f0y);
            p1r[k] = make_float2(xv.x * f1x, xv.y * f1y);
            csx0 += p0r[k].x; csy0 += p0r[k].y;
            csx1 += p1r[k].x; csy1 += p1r[k].y;
        }

#pragma unroll 1
        for (int g = 0; g < 6; g++) {
            const int rbase = h0 + g * 5 + 2;
            // batch-prefetch 5 x rows (MLP 5, DRAM)
            float2 xn[5];
#pragma unroll
            for (int k = 0; k < 5; k++) {
                int r = rbase + k;
                int rc = r > 255 ? 255 : r;
                xn[k] = __ldg((const float2*)(xc + (rc << 8)));
            }
#pragma unroll
            for (int k = 0; k < 5; k++) {
                const int sn = (k + 4) % 5;     // slot being replaced
                const int sc = (k + 2) % 5;     // center-row slot
                // remove departing row
                csx0 -= p0r[sn].x; csy0 -= p0r[sn].y;
                csx1 -= p1r[sn].x; csy1 -= p1r[sn].y;
                // fold in new row (L2-resident fv plane)
                int r = rbase + k;
                int rc = r > 255 ? 255 : r;
                float2 fv = __ldg((const float2*)(fvp + (rc << 8)));
                if (!(colv && r <= 255)) { fv.x = 0.f; fv.y = 0.f; }
                float f1x = fmaxf(fv.x, 0.f), f1y = fmaxf(fv.y, 0.f);
                float f0x = f1x - fv.x, f0y = f1y - fv.y;
                float2 q0 = make_float2(xn[k].x * f0x, xn[k].y * f0y);
                float2 q1 = make_float2(xn[k].x * f1x, xn[k].y * f1y);
                p0r[sn] = q0; p1r[sn] = q1;
                csx0 += q0.x; csy0 += q0.y;
                csx1 += q1.x; csy1 += q1.y;
                // horizontal halo via shuffles (both classes)
                float u0x = __shfl_up_sync(FULLMASK, csx0, 1);
                float u0y = __shfl_up_sync(FULLMASK, csy0, 1);
                float d0x = __shfl_down_sync(FULLMASK, csx0, 1);
                float d0y = __shfl_down_sync(FULLMASK, csy0, 1);
                float u1x = __shfl_up_sync(FULLMASK, csx1, 1);
                float u1y = __shfl_up_sync(FULLMASK, csy1, 1);
                float d1x = __shfl_down_sync(FULLMASK, csx1, 1);
                float d1y = __shfl_down_sync(FULLMASK, csy1, 1);
                // masked epilogue
                int h = h0 + g * 5 + k;
                int hc = h > 255 ? 255 : h;
                float2 s2 = __ldg((const float2*)(ivp + (hc << 8)));
                if (!(qv && h <= 255)) { s2.x = 0.f; s2.y = 0.f; }
                if (s2.x != 0.f) {              // col wl: window wl-2..wl+2
                    bool pos = s2.x > 0.f;
                    float Px = pos ? u1x : u0x;
                    float Py = pos ? u1y : u0y;
                    float Cx = pos ? csx1 : csx0;
                    float Cy = pos ? csy1 : csy0;
                    float Nx = pos ? d1x : d0x;
                    float S = Px + Py + Cx + Cy + Nx;
                    float cen = p0r[sc].x + p1r[sc].x;  // = x (corr=1 here)
                    float ring = S - cen;
                    float dd = fmaf(-ring, fabsf(s2.x), cen);
                    float q = dd * dd;
                    if (pos) acc1 += q; else acc0 += q;
                }
                if (s2.y != 0.f) {              // col wl+1: window wl-1..wl+3
                    bool pos = s2.y > 0.f;
                    float Py = pos ? u1y : u0y;
                    float Cx = pos ? csx1 : csx0;
                    float Cy = pos ? csy1 : csy0;
                    float Nx = pos ? d1x : d0x;
                    float Ny = pos ? d1y : d0y;
                    float S = Py + Cx + Cy + Nx + Ny;
                    float cen = p0r[sc].y + p1r[sc].y;
                    float ring = S - cen;
                    float dd = fmaf(-ring, fabsf(s2.y), cen);
                    float q = dd * dd;
                    if (pos) acc1 += q; else acc0 += q;
                }
            }
        }
    }

    // warp reduce, then one block reduce + 2 double atomics per block
#pragma unroll
    for (int o = 16; o; o >>= 1) {
        acc0 += __shfl_xor_sync(FULLMASK, acc0, o);
        acc1 += __shfl_xor_sync(FULLMASK, acc1, o);
    }
    if (lane == 0) { sred[0][wid] = (double)acc0; sred[1][wid] = (double)acc1; }
    __syncthreads();
    if (threadIdx.x == 0) {
        double t0 = 0.0, t1 = 0.0;
#pragma unroll
        for (int i = 0; i < 8; i++) { t0 += sred[0][i]; t1 += sred[1][i]; }
        atomicAdd(&g_loss[0], t0);
        atomicAdd(&g_loss[1], t1);
    }
}

// ---------------- Kernel D: finalize ---------------------------------------
__global__ void kernD(float* out) {
    double total = 0.0;
    int ncls = 0;
#pragma unroll
    for (int c = 0; c < 2; c++) {
        bool valid = (g_cal[c] >= 1) && (g_nsel[c] >= 1);
        double denom = (double)g_nsel[c] * 256.0;
        if (denom < 1.0) denom = 1.0;
        double lc = g_loss[c] / denom;
        if (valid) { total += lc; ncls++; }
    }
    out[0] = (ncls == 0) ? 0.0f : (float)(total / (double)ncls);
}

extern "C" void kernel_launch(void* const* d_in, const int* in_sizes, int n_in,
                              void* d_out, int out_size) {
    const float* xfeat = (const float*)d_in[0];   // [4,256,256,256] f32
    const float* clf   = (const float*)d_in[1];   // [4,2,256,256]   f32
    const int*   gt    = (const int*)d_in[2];     // [4,256,256]     i32
    float* out = (float*)d_out;

    kernA<<<NPIX / 256, 256>>>(gt, clf);
    kernB<<<NPIX / 256, 256>>>();
    // 5760 warp-tasks = 5 wband x 9 hband x 4 b x 32 chunk -> 720 blocks x 8 warps
    kernC<<<720, 256>>>(xfeat);
    kernD<<<1, 1>>>(out);
}

// round 6
// speedup vs baseline: 1.8230x; 1.3079x over previous
#include <cuda_runtime.h>

#define BB 4
#define CC 256
#define HH 256
#define WW 256
#define HWSZ (HH * WW)
#define NPIX (BB * HWSZ)
#define FULLMASK 0xFFFFFFFFu

#define NBLK 444
#define NTHR 256
#define NTH_TOT (NBLK * NTHR)          // 113664 threads
#define NWARP (NBLK * 8)               // 3552 warps
#define NTASK (5 * 9 * 4 * 256)        // 46080 warp-tasks
#define PROWS 260                      // 2 zero rows top + 256 + 2 zero rows bottom
#define PPITCH 128                     // float2 pairs per row

// intermediates
__device__ unsigned char g_info[NPIX];
// fv plane: row r of image stored at plane row r+2; fv = +-1 if correct (sign=class) else 0
__device__ float2 g_fvp[BB * PROWS * PPITCH];
// iv plane: iv of image row h stored at plane row h+2; iv = +-1/(cnt+1e-5) if mse-masked (sign=class) else 0
__device__ float2 g_ivp[BB * PROWS * PPITCH];
__device__ double g_loss[2];
__device__ int g_nsel[2], g_cal[2];
__device__ int g_bar_count = 0;
__device__ volatile int g_bar_gen = 0;

__device__ __forceinline__ void gridsync() {
    __syncthreads();
    if (threadIdx.x == 0) {
        __threadfence();
        int gen = g_bar_gen;
        if (atomicAdd(&g_bar_count, 1) == NBLK - 1) {
            g_bar_count = 0;
            __threadfence();
            g_bar_gen = gen + 1;
        } else {
            while (g_bar_gen == gen) { __nanosleep(64); }
        }
        __threadfence();
    }
    __syncthreads();
}

__global__ void __launch_bounds__(NTHR, 3) kernFused(
    const float* __restrict__ x, const float* __restrict__ clf,
    const int* __restrict__ gt, float* __restrict__ out) {
    __shared__ double sred[2][8];
    const int tid0 = blockIdx.x * NTHR + threadIdx.x;

    // ================= Phase 1a: per-pixel info (pred, correct, edge) ======
    for (int p = tid0; p < NPIX; p += NTH_TOT) {
        if (p == 0) {
            g_loss[0] = 0.0; g_loss[1] = 0.0;
            g_nsel[0] = 0; g_nsel[1] = 0;
            g_cal[0] = 0; g_cal[1] = 0;
        }
        int b = p >> 16;
        int hw = p & (HWSZ - 1);
        int h = hw >> 8;
        int w = hw & (WW - 1);
        int g = gt[p];
        float c0 = clf[(size_t)(b * 2) * HWSZ + hw];
        float c1 = clf[(size_t)(b * 2 + 1) * HWSZ + hw];
        int pred = (c1 > c0) ? 1 : 0;          // argmax ties -> index 0
        int correct = (pred == g) ? 1 : 0;
        int edge = (g == -1) ? 1 : 0;
        if (h < HH - 5) edge |= (gt[p + 5 * WW] != g) ? 1 : 0;
        if (w < WW - 5) edge |= (gt[p + 5] != g) ? 1 : 0;
        g_info[p] = (unsigned char)((g & 1) | (correct << 1) | (edge << 2));
    }
    gridsync();

    // ================= Phase 1b: ring counts -> fv/iv planes + counters ====
    for (int p = tid0; p < NPIX; p += NTH_TOT) {
        int b = p >> 16;
        int hw = p & (HWSZ - 1);
        int h = hw >> 8;
        int w = hw & (WW - 1);
        unsigned info = g_info[p];
        int g = info & 1;
        int correct = (info >> 1) & 1;
        int edge = (info >> 2) & 1;
        int cntCorr = 0, cntCls = 0;
#pragma unroll
        for (int dh = -2; dh <= 2; dh++) {
#pragma unroll
            for (int dw = -2; dw <= 2; dw++) {
                if (dh == 0 && dw == 0) continue;
                int hh = h + dh, wp = w + dw;
                if ((unsigned)hh < HH && (unsigned)wp < WW) {
                    unsigned qi = g_info[p + dh * WW + dw];
                    int same = ((int)(qi & 1) == g) ? 1 : 0;
                    cntCls += same;
                    cntCorr += same & (int)((qi >> 1) & 1);
                }
            }
        }
        int mse = correct & edge & (cntCorr >= 1 ? 1 : 0);
        int cal = edge & (cntCls >= 1 ? 1 : 0);

        float fv = correct ? (g ? 1.0f : -1.0f) : 0.0f;
        float inv = 1.0f / ((float)cntCorr + 1e-5f);
        float ivs = mse ? (g ? inv : -inv) : 0.0f;

        float* fvf = (float*)(g_fvp + (size_t)b * (PROWS * PPITCH));
        float* ivf = (float*)(g_ivp + (size_t)b * (PROWS * PPITCH));
        int col = w;                           // scalar float index within row = w
        fvf[(h + 2) * WW + col] = fv;
        ivf[(h + 2) * WW + col] = ivs;
        if (h < 2) {                           // zero pad rows 0,1
            fvf[h * WW + col] = 0.0f;
            ivf[h * WW + col] = 0.0f;
        }
        if (h >= HH - 2) {                     // zero pad rows 258,259
            fvf[(h + 4) * WW + col] = 0.0f;
            ivf[(h + 4) * WW + col] = 0.0f;
        }

        unsigned bm;
        bm = __ballot_sync(FULLMASK, mse && g == 0);
        if ((threadIdx.x & 31) == 0 && bm) atomicAdd(&g_nsel[0], __popc(bm));
        bm = __ballot_sync(FULLMASK, mse && g == 1);
        if ((threadIdx.x & 31) == 0 && bm) atomicAdd(&g_nsel[1], __popc(bm));
        bm = __ballot_sync(FULLMASK, cal && g == 0);
        if ((threadIdx.x & 31) == 0 && bm) atomicAdd(&g_cal[0], __popc(bm));
        bm = __ballot_sync(FULLMASK, cal && g == 1);
        if ((threadIdx.x & 31) == 0 && bm) atomicAdd(&g_cal[1], __popc(bm));
    }
    gridsync();

    // ================= Phase 2: separable 2-class box filter ===============
    // Warp-task = (wband, hband, b, ch): 30 output rows x 60 output cols of one
    // channel. Lane covers float2 cols wl = w0-2+2*lane; lanes 1..30 output.
    // (u,v) = column 5-row sums of (x*|fv|, x*fv); per-class sum = (u +- v)/2.
    // 5-slot register ring; all row-validity handled by zero-padded planes.
    const int lane = threadIdx.x & 31;
    const int wid = threadIdx.x >> 5;
    const int gwarp = blockIdx.x * 8 + wid;
    float acc0 = 0.f, acc1 = 0.f;

#pragma unroll 1
    for (int t = gwarp; t < NTASK; t += NWARP) {
        int wband = t % 5;
        int r1 = t / 5;
        int hband = r1 % 9;
        int r2 = r1 / 9;
        int b = r2 & 3;
        int ch = r2 >> 2;
        int h0 = hband * 30;
        int w0 = wband * 60;
        int wl = w0 - 2 + (lane << 1);
        bool colv = (wl >= 0) && (wl <= 254);
        int wc = colv ? wl : (wl < 0 ? 0 : 254);
        float colm = colv ? 1.0f : 0.0f;
        float qvm = (colv && lane >= 1 && lane <= 30) ? 1.0f : 0.0f;

        const float* xc = x + (((size_t)(b * CC + ch)) << 16) + wc;
        const float2* fvb = g_fvp + (size_t)b * (PROWS * PPITCH) + (wc >> 1);
        const float2* ivb = g_ivp + (size_t)b * (PROWS * PPITCH) + (wc >> 1);

        float2 ptr_[5], psr_[5];
        float ux = 0.f, uy = 0.f, vx = 0.f, vy = 0.f;

        // prologue rows h0-2..h0+1 -> ring slots 0..3
#pragma unroll
        for (int k = 0; k < 4; k++) {
            int r = h0 - 2 + k;
            int rcx = r < 0 ? 0 : r;
            float2 xv = __ldg((const float2*)(xc + (rcx << 8)));
            float2 fv = __ldcg(fvb + (r + 2) * PPITCH);
            float fx = fv.x * colm, fy = fv.y * colm;
            float2 pt = make_float2(xv.x * fabsf(fx), xv.y * fabsf(fy));
            float2 ps = make_float2(xv.x * fx, xv.y * fy);
            ptr_[k] = pt; psr_[k] = ps;
            ux += pt.x; uy += pt.y; vx += ps.x; vy += ps.y;
        }
        ptr_[4] = make_float2(0.f, 0.f);
        psr_[4] = make_float2(0.f, 0.f);

#pragma unroll 1
        for (int g = 0; g < 6; g++) {
            int rbase = h0 + 2 + g * 5;
            float2 xn[5], fvn[5], ivn[5];
#pragma unroll
            for (int k = 0; k < 5; k++) {
                int r = rbase + k;                 // <= 271
                int rcx = r > 255 ? 255 : r;
                int rcf = r > 257 ? 259 : r + 2;   // zero rows for r>255
                int rci = r > 259 ? 259 : r;       // iv plane row r (zero > 257)
                xn[k] = __ldg((const float2*)(xc + (rcx << 8)));
                fvn[k] = __ldcg(fvb + rcf * PPITCH);
                ivn[k] = __ldcg(ivb + rci * PPITCH);
            }
#pragma unroll
            for (int k = 0; k < 5; k++) {
                const int sn = (k + 4) % 5;        // departing slot
                const int sc = (k + 2) % 5;        // center-row slot
                ux -= ptr_[sn].x; uy -= ptr_[sn].y;
                vx -= psr_[sn].x; vy -= psr_[sn].y;
                float fx = fvn[k].x * colm, fy = fvn[k].y * colm;
                float2 pt = make_float2(xn[k].x * fabsf(fx), xn[k].y * fabsf(fy));
                float2 ps = make_float2(xn[k].x * fx, xn[k].y * fy);
                ptr_[sn] = pt; psr_[sn] = ps;
                ux += pt.x; uy += pt.y; vx += ps.x; vy += ps.y;
                // horizontal halo via shuffles
                float ulx = __shfl_up_sync(FULLMASK, ux, 1);
                float uly = __shfl_up_sync(FULLMASK, uy, 1);
                float urx = __shfl_down_sync(FULLMASK, ux, 1);
                float ury = __shfl_down_sync(FULLMASK, uy, 1);
                float vlx = __shfl_up_sync(FULLMASK, vx, 1);
                float vly = __shfl_up_sync(FULLMASK, vy, 1);
                float vrx = __shfl_down_sync(FULLMASK, vx, 1);
                float vry = __shfl_down_sync(FULLMASK, vy, 1);
                float cu = uly + ux + uy + urx;
                float cw = vly + vx + vy + vrx;
                float u50 = ulx + cu, u51 = cu + ury;
                float v50 = vlx + cw, v51 = cw + vry;
                // epilogue (no selects; class via sign of s2)
                float s20 = ivn[k].x * qvm;
                float s21 = ivn[k].y * qvm;
                float cen0 = ptr_[sc].x, cen1 = ptr_[sc].y;
                float a0 = fabsf(s20), a1 = fabsf(s21);
                float t10 = fmaf(0.5f, u50, -cen0);
                float t11 = fmaf(0.5f, u51, -cen1);
                float dd0 = fmaf(-0.5f * s20, v50, fmaf(-t10, a0, cen0));
                float dd1 = fmaf(-0.5f * s21, v51, fmaf(-t11, a1, cen1));
                float q0 = dd0 * dd0, q1 = dd1 * dd1;
                if (s20 > 0.f) acc1 += q0; else if (s20 < 0.f) acc0 += q0;
                if (s21 > 0.f) acc1 += q1; else if (s21 < 0.f) acc0 += q1;
            }
        }
    }

    // block reduction -> 2 double atomics per block
#pragma unroll
    for (int o = 16; o; o >>= 1) {
        acc0 += __shfl_xor_sync(FULLMASK, acc0, o);
        acc1 += __shfl_xor_sync(FULLMASK, acc1, o);
    }
    if (lane == 0) { sred[0][wid] = (double)acc0; sred[1][wid] = (double)acc1; }
    __syncthreads();
    if (threadIdx.x == 0) {
        double t0 = 0.0, t1 = 0.0;
#pragma unroll
        for (int i = 0; i < 8; i++) { t0 += sred[0][i]; t1 += sred[1][i]; }
        atomicAdd(&g_loss[0], t0);
        atomicAdd(&g_loss[1], t1);
    }
    gridsync();

    // ================= Phase 3: finalize ====================================
    if (blockIdx.x == 0 && threadIdx.x == 0) {
        double total = 0.0;
        int ncls = 0;
#pragma unroll
        for (int c = 0; c < 2; c++) {
            int ns = *(volatile int*)&g_nsel[c];
            int ca = *(volatile int*)&g_cal[c];
            double ls = *(volatile double*)&g_loss[c];
            bool valid = (ca >= 1) && (ns >= 1);
            double denom = (double)ns * 256.0;
            if (denom < 1.0) denom = 1.0;
            if (valid) { total += ls / denom; ncls++; }
        }
        out[0] = (ncls == 0) ? 0.0f : (float)(total / (double)ncls);
    }
}

extern "C" void kernel_launch(void* const* d_in, const int* in_sizes, int n_in,
                              void* d_out, int out_size) {
    const float* xfeat = (const float*)d_in[0];   // [4,256,256,256] f32
    const float* clf   = (const float*)d_in[1];   // [4,2,256,256]   f32
    const int*   gt    = (const int*)d_in[2];     // [4,256,256]     i32
    float* out = (float*)d_out;

    kernFused<<<NBLK, NTHR>>>(xfeat, clf, gt, out);
}

// round 7
// speedup vs baseline: 2.0347x; 1.1162x over previous
#include <cuda_runtime.h>

#define BB 4
#define CC 256
#define HH 256
#define WW 256
#define HWSZ (HH * WW)
#define NPIX (BB * HWSZ)
#define FULLMASK 0xFFFFFFFFu

#define NBLK 592
#define NTHR 256
#define NTH_TOT (NBLK * NTHR)          // 151552 threads
#define NWARP (NBLK * 8)               // 4736 warps
#define NTASK (5 * 9 * 4 * 256)        // 46080 warp-tasks
#define PROWS 274                      // rows 0,1 + 2..257 data + 258..273 zero
#define PPITCH 128                     // float2 per plane row
#define PLSZ (PROWS * PPITCH)
#define ZROW 258                       // first guaranteed-zero bottom pad row

// intermediates
__device__ unsigned char g_info[NPIX];
// fv plane: image row h stored at plane row h+2; fv = +-1 if correct (sign=class) else 0
__device__ float2 g_fvp[BB * PLSZ];
// iv plane: image row h stored at plane row h+2; iv = +-1/(cnt+1e-5) if mse-masked else 0
__device__ float2 g_ivp[BB * PLSZ];
__device__ double g_loss[2];
__device__ int g_nsel[2], g_cal[2];
__device__ int g_bar_count = 0;
__device__ volatile int g_bar_gen = 0;

__device__ __forceinline__ void gridsync() {
    __syncthreads();
    if (threadIdx.x == 0) {
        __threadfence();
        int gen = g_bar_gen;
        if (atomicAdd(&g_bar_count, 1) == NBLK - 1) {
            g_bar_count = 0;
            __threadfence();
            g_bar_gen = gen + 1;
        } else {
            while (g_bar_gen == gen) { __nanosleep(64); }
        }
        __threadfence();
    }
    __syncthreads();
}

__global__ void __launch_bounds__(NTHR, 4) kernFused(
    const float* __restrict__ x, const float* __restrict__ clf,
    const int* __restrict__ gt, float* __restrict__ out) {
    __shared__ double sred[2][8];
    const int tid0 = blockIdx.x * NTHR + threadIdx.x;

    // ================= Phase 1a: per-pixel info + plane pad zeroing =========
    for (int i = tid0; i < BB * 18 * WW; i += NTH_TOT) {
        int col = i & 255;
        int j = (i >> 8) % 18;
        int b = (i >> 8) / 18;
        int row = (j < 2) ? j : (j + 256);      // rows 0,1,258..273
        ((float*)(g_fvp + (size_t)b * PLSZ))[row * WW + col] = 0.f;
        ((float*)(g_ivp + (size_t)b * PLSZ))[row * WW + col] = 0.f;
    }
    for (int p = tid0; p < NPIX; p += NTH_TOT) {
        if (p == 0) {
            g_loss[0] = 0.0; g_loss[1] = 0.0;
            g_nsel[0] = 0; g_nsel[1] = 0;
            g_cal[0] = 0; g_cal[1] = 0;
        }
        int b = p >> 16;
        int hw = p & (HWSZ - 1);
        int h = hw >> 8;
        int w = hw & (WW - 1);
        int g = gt[p];
        float c0 = clf[(size_t)(b * 2) * HWSZ + hw];
        float c1 = clf[(size_t)(b * 2 + 1) * HWSZ + hw];
        int pred = (c1 > c0) ? 1 : 0;          // argmax ties -> index 0
        int correct = (pred == g) ? 1 : 0;
        int edge = (g == -1) ? 1 : 0;
        if (h < HH - 5) edge |= (gt[p + 5 * WW] != g) ? 1 : 0;
        if (w < WW - 5) edge |= (gt[p + 5] != g) ? 1 : 0;
        g_info[p] = (unsigned char)((g & 1) | (correct << 1) | (edge << 2));
    }
    gridsync();

    // ================= Phase 1b: ring counts -> fv/iv planes + counters =====
    for (int p = tid0; p < NPIX; p += NTH_TOT) {
        int b = p >> 16;
        int hw = p & (HWSZ - 1);
        int h = hw >> 8;
        int w = hw & (WW - 1);
        unsigned info = g_info[p];
        int g = info & 1;
        int correct = (info >> 1) & 1;
        int edge = (info >> 2) & 1;
        int cntCorr = 0, cntCls = 0;
#pragma unroll
        for (int dh = -2; dh <= 2; dh++) {
#pragma unroll
            for (int dw = -2; dw <= 2; dw++) {
                if (dh == 0 && dw == 0) continue;
                int hh = h + dh, wp = w + dw;
                if ((unsigned)hh < HH && (unsigned)wp < WW) {
                    unsigned qi = g_info[p + dh * WW + dw];
                    int same = ((int)(qi & 1) == g) ? 1 : 0;
                    cntCls += same;
                    cntCorr += same & (int)((qi >> 1) & 1);
                }
            }
        }
        int mse = correct & edge & (cntCorr >= 1 ? 1 : 0);
        int cal = edge & (cntCls >= 1 ? 1 : 0);

        float fv = correct ? (g ? 1.0f : -1.0f) : 0.0f;
        float inv = 1.0f / ((float)cntCorr + 1e-5f);
        float ivs = mse ? (g ? inv : -inv) : 0.0f;

        ((float*)(g_fvp + (size_t)b * PLSZ))[(h + 2) * WW + w] = fv;
        ((float*)(g_ivp + (size_t)b * PLSZ))[(h + 2) * WW + w] = ivs;

        unsigned bm;
        bm = __ballot_sync(FULLMASK, mse && g == 0);
        if ((threadIdx.x & 31) == 0 && bm) atomicAdd(&g_nsel[0], __popc(bm));
        bm = __ballot_sync(FULLMASK, mse && g == 1);
        if ((threadIdx.x & 31) == 0 && bm) atomicAdd(&g_nsel[1], __popc(bm));
        bm = __ballot_sync(FULLMASK, cal && g == 0);
        if ((threadIdx.x & 31) == 0 && bm) atomicAdd(&g_cal[0], __popc(bm));
        bm = __ballot_sync(FULLMASK, cal && g == 1);
        if ((threadIdx.x & 31) == 0 && bm) atomicAdd(&g_cal[1], __popc(bm));
    }
    gridsync();

    // ================= Phase 2: separable 2-class box filter ================
    const int lane = threadIdx.x & 31;
    const int wid = threadIdx.x >> 5;
    const int gwarp = blockIdx.x * 8 + wid;
    float acc0 = 0.f, acc1 = 0.f;

#pragma unroll 1
    for (int t = gwarp; t < NTASK; t += NWARP) {
        int wband = t % 5;
        int r1 = t / 5;
        int hband = r1 % 9;
        int r2 = r1 / 9;
        int b = r2 & 3;
        int ch = r2 >> 2;
        int h0 = hband * 30;
        int wl = wband * 60 - 2 + (lane << 1);
        bool colv = (wl >= 0) && (wl <= 254);
        bool qv = colv && (lane >= 1) && (lane <= 30);
        int wc = colv ? wl : (wl < 0 ? 0 : 254);
        int pc = wc >> 1;                       // float2 col in planes

        const float* xc = x + ((size_t)(b * CC + ch) << 16) + wc;
        const float2* plb = g_fvp + (size_t)b * PLSZ;
        const float2* ilb = g_ivp + (size_t)b * PLSZ;
        // main-loop plane pointers: park invalid lanes on a zero row, stride 0
        const float2* fvp = colv ? (plb + (h0 + 4) * PPITCH + pc) : (plb + ZROW * PPITCH);
        const float2* ivp = qv ? (ilb + (h0 + 2) * PPITCH + pc) : (ilb + ZROW * PPITCH);
        const int fstep = colv ? 5 * PPITCH : 0;
        const int istep = qv ? 5 * PPITCH : 0;

        float2 pt[5], ps[5];
        float ux = 0.f, uy = 0.f, vx = 0.f, vy = 0.f;

        // prologue rows h0-2..h0+1 -> ring slots 0..3 (fv plane rows h0..h0+3)
        const float2* fvpro = colv ? (plb + h0 * PPITCH + pc) : (plb + ZROW * PPITCH);
#pragma unroll
        for (int k = 0; k < 4; k++) {
            int r = h0 - 2 + k;
            int rc = r < 0 ? 0 : r;
            float2 xv = __ldg((const float2*)(xc + (rc << 8)));
            float2 fv = __ldg(fvpro + k * PPITCH);
            float2 npt = make_float2(xv.x * fabsf(fv.x), xv.y * fabsf(fv.y));
            float2 nps = make_float2(xv.x * fv.x, xv.y * fv.y);
            pt[k] = npt; ps[k] = nps;
            ux += npt.x; uy += npt.y; vx += nps.x; vy += nps.y;
        }
        pt[4] = make_float2(0.f, 0.f);
        ps[4] = make_float2(0.f, 0.f);

#pragma unroll 1
        for (int g = 0; g < 6; g++) {
            const int rbase = h0 + 2 + g * 5;
            // batch-prefetch the 5 DRAM x rows (MLP 5)
            float2 xn[5];
#pragma unroll
            for (int k = 0; k < 5; k++) {
                int r = rbase + k;
                int rc = r > 255 ? 255 : r;
                xn[k] = __ldg((const float2*)(xc + (rc << 8)));
            }
#pragma unroll
            for (int k = 0; k < 5; k++) {
                const int sn = (k + 4) % 5;    // departing slot
                const int sc = (k + 2) % 5;    // center-row slot
                // L2-resident plane loads, immediate offsets (issued early)
                float2 fv = __ldg(fvp + k * PPITCH);
                float2 iv = __ldg(ivp + k * PPITCH);
                ux -= pt[sn].x; uy -= pt[sn].y;
                vx -= ps[sn].x; vy -= ps[sn].y;
                float2 npt = make_float2(xn[k].x * fabsf(fv.x), xn[k].y * fabsf(fv.y));
                float2 nps = make_float2(xn[k].x * fv.x, xn[k].y * fv.y);
                pt[sn] = npt; ps[sn] = nps;
                ux += npt.x; uy += npt.y; vx += nps.x; vy += nps.y;
                // horizontal halo via shuffles
                float ulx = __shfl_up_sync(FULLMASK, ux, 1);
                float uly = __shfl_up_sync(FULLMASK, uy, 1);
                float urx = __shfl_down_sync(FULLMASK, ux, 1);
                float ury = __shfl_down_sync(FULLMASK, uy, 1);
                float vlx = __shfl_up_sync(FULLMASK, vx, 1);
                float vly = __shfl_up_sync(FULLMASK, vy, 1);
                float vrx = __shfl_down_sync(FULLMASK, vx, 1);
                float vry = __shfl_down_sync(FULLMASK, vy, 1);
                float cu = uly + ux + uy + urx;
                float cw = vly + vx + vy + vrx;
                float u50 = ulx + cu, u51 = cu + ury;
                float v50 = vlx + cw, v51 = cw + vry;
                // epilogue; class = sign(iv), zero iv -> no accumulation
                float s20 = iv.x, s21 = iv.y;
                float cen0 = pt[sc].x, cen1 = pt[sc].y;   // = x at masked px
                float a0 = fabsf(s20), a1 = fabsf(s21);
                float t10 = fmaf(0.5f, u50, -cen0);
                float t11 = fmaf(0.5f, u51, -cen1);
                float dd0 = fmaf(-0.5f * s20, v50, fmaf(-t10, a0, cen0));
                float dd1 = fmaf(-0.5f * s21, v51, fmaf(-t11, a1, cen1));
                float q0 = dd0 * dd0, q1 = dd1 * dd1;
                if (s20 > 0.f) acc1 += q0; else if (s20 < 0.f) acc0 += q0;
                if (s21 > 0.f) acc1 += q1; else if (s21 < 0.f) acc0 += q1;
            }
            fvp += fstep;
            ivp += istep;
        }
    }

    // block reduction -> 2 double atomics per block
#pragma unroll
    for (int o = 16; o; o >>= 1) {
        acc0 += __shfl_xor_sync(FULLMASK, acc0, o);
        acc1 += __shfl_xor_sync(FULLMASK, acc1, o);
    }
    if (lane == 0) { sred[0][wid] = (double)acc0; sred[1][wid] = (double)acc1; }
    __syncthreads();
    if (threadIdx.x == 0) {
        double t0 = 0.0, t1 = 0.0;
#pragma unroll
        for (int i = 0; i < 8; i++) { t0 += sred[0][i]; t1 += sred[1][i]; }
        atomicAdd(&g_loss[0], t0);
        atomicAdd(&g_loss[1], t1);
    }
    gridsync();

    // ================= Phase 3: finalize =====================================
    if (blockIdx.x == 0 && threadIdx.x == 0) {
        double total = 0.0;
        int ncls = 0;
#pragma unroll
        for (int c = 0; c < 2; c++) {
            int ns = *(volatile int*)&g_nsel[c];
            int ca = *(volatile int*)&g_cal[c];
            double ls = *(volatile double*)&g_loss[c];
            bool valid = (ca >= 1) && (ns >= 1);
            double denom = (double)ns * 256.0;
            if (denom < 1.0) denom = 1.0;
            if (valid) { total += ls / denom; ncls++; }
        }
        out[0] = (ncls == 0) ? 0.0f : (float)(total / (double)ncls);
    }
}

extern "C" void kernel_launch(void* const* d_in, const int* in_sizes, int n_in,
                              void* d_out, int out_size) {
    const float* xfeat = (const float*)d_in[0];   // [4,256,256,256] f32
    const float* clf   = (const float*)d_in[1];   // [4,2,256,256]   f32
    const int*   gt    = (const int*)d_in[2];     // [4,256,256]     i32
    float* out = (float*)d_out;

    kernFused<<<NBLK, NTHR>>>(xfeat, clf, gt, out);
}